// round 9
// baseline (speedup 1.0000x reference)
#include <cuda_runtime.h>
#include <math.h>

// ---------------- problem constants ----------------
#define Nn    20000
#define Ee    640000
#define Pp    27
#define Mm    5000
#define MAXNb 64
#define KIN   64
#define PIN   (Pp * KIN)      // 1728
#define R2c   0.01f
#define NC    512             // 8x8x8 spatial cells
#define CL    8               // FPS cluster size (one x-slab per CTA)
#define SLAB_MAX 3072         // max points per slab (mean 2500)

// output section offsets (flattened float32 tuple concat)
#define SEC_X     0
#define SEC_COL   320000
#define SEC_ROW   640000
#define SEC_POS   960000
#define SEC_BATCH 975000
#define SEC_EA    980000

// ---------------- persistent device scratch ----------------
__device__ __align__(16) float4 g_pos4[Nn];   // x,y,z, |p|^2
__device__ int    g_idx[Mm];
__device__ int    g_pcell[Nn];
__device__ int    g_cellcnt[NC];
__device__ int    g_cellstart[NC + 1];
__device__ int    g_cellfill[NC];
__device__ __align__(16) float4 g_spos[Nn];   // cell-sorted: x,y,z, orig idx bits
__device__ __align__(16) float g_accN[(size_t)Nn * PIN];  // 138 MB, all nodes
__device__ float  g_degN[Nn];

// ---------------- launch 1: pos4 + cell id + histogram (single block) ----------------
__global__ void __launch_bounds__(1024) prep1b_kernel(const float* __restrict__ pos) {
    int tid = threadIdx.x;
    if (tid < NC) g_cellcnt[tid] = 0;
    __syncthreads();
    for (int i = tid; i < Nn; i += 1024) {
        float x = pos[3 * i], y = pos[3 * i + 1], z = pos[3 * i + 2];
        float an = __fadd_rn(__fadd_rn(__fmul_rn(x, x), __fmul_rn(y, y)),
                             __fmul_rn(z, z));
        g_pos4[i] = make_float4(x, y, z, an);
        int cx = min((int)(x * 8.0f), 7);
        int cy = min((int)(y * 8.0f), 7);
        int cz = min((int)(z * 8.0f), 7);
        int cid = (cx << 6) | (cy << 3) | cz;
        g_pcell[i] = cid;
        atomicAdd(&g_cellcnt[cid], 1);
    }
}

// ---------------- launch 2: exclusive scan of cell counts ----------------
__global__ void cell_scan_kernel() {
    __shared__ int sh[NC];
    int tid = threadIdx.x;
    int v = g_cellcnt[tid];
    sh[tid] = v;
    __syncthreads();
    for (int o = 1; o < NC; o <<= 1) {
        int t = (tid >= o) ? sh[tid - o] : 0;
        __syncthreads();
        sh[tid] += t;
        __syncthreads();
    }
    g_cellstart[tid + 1] = sh[tid];
    g_cellfill[tid] = sh[tid] - v;
    if (tid == 0) g_cellstart[0] = 0;
}

// ---------------- launch 3: cell scatter + zero acc/deg (fused) ----------------
#define ZB 33750   // 33750*256 float4 = Nn*PIN floats
__global__ void scatter_zero_kernel(const float* __restrict__ pos) {
    int i = blockIdx.x * blockDim.x + threadIdx.x;
    if (i < Nn) {
        int cid = g_pcell[i];
        int off = atomicAdd(&g_cellfill[cid], 1);
        g_spos[off] = make_float4(pos[3 * i], pos[3 * i + 1], pos[3 * i + 2],
                                  __int_as_float(i));
        g_degN[i] = 0.0f;
    }
    reinterpret_cast<float4*>(g_accN)[i] = make_float4(0.f, 0.f, 0.f, 0.f);
}

// ---------------- FPS cluster helpers ----------------
__device__ __forceinline__ unsigned smem_u32(const void* p) {
    unsigned a;
    asm("{ .reg .u64 t; cvta.to.shared.u64 t, %1; cvt.u32.u64 %0, t; }"
        : "=r"(a) : "l"(p));
    return a;
}
__device__ __forceinline__ unsigned cl_rank() {
    unsigned r;
    asm("mov.u32 %0, %%cluster_ctarank;" : "=r"(r));
    return r;
}
#define CL_SYNC() do { \
    asm volatile("barrier.cluster.arrive.aligned;" ::: "memory"); \
    asm volatile("barrier.cluster.wait.aligned;" ::: "memory"); } while (0)

#define MBAR_WAIT_CLUSTER(mbar, par) do { \
    asm volatile("{\n\t.reg .pred p;\n\t" \
        "WAITC_%=:\n\t" \
        "mbarrier.try_wait.parity.acquire.cluster.shared::cta.b64 p, [%0], %1;\n\t" \
        "@p bra.uni DONEC_%=;\n\t" \
        "bra.uni WAITC_%=;\n\t" \
        "DONEC_%=:\n\t}" :: "r"(mbar), "r"(par) : "memory"); } while (0)

__device__ __forceinline__ void dsmem_push_slot(unsigned slot_addr, unsigned mbar_addr,
                                                unsigned target,
                                                unsigned long long key,
                                                float x, float y, float z) {
    unsigned rs, rb;
    asm volatile("mapa.shared::cluster.u32 %0, %1, %2;"
                 : "=r"(rs) : "r"(slot_addr), "r"(target));
    asm volatile("mapa.shared::cluster.u32 %0, %1, %2;"
                 : "=r"(rb) : "r"(mbar_addr), "r"(target));
    asm volatile("st.shared::cluster.u64 [%0], %1;" :: "r"(rs), "l"(key) : "memory");
    asm volatile("st.shared::cluster.b32 [%0], %1;" :: "r"(rs + 8),  "r"(__float_as_uint(x)) : "memory");
    asm volatile("st.shared::cluster.b32 [%0], %1;" :: "r"(rs + 12), "r"(__float_as_uint(y)) : "memory");
    asm volatile("st.shared::cluster.b32 [%0], %1;" :: "r"(rs + 16), "r"(__float_as_uint(z)) : "memory");
    asm volatile("mbarrier.arrive.release.cluster.shared::cluster.b64 _, [%0];"
                 :: "r"(rb) : "memory");
}

// ---------------- FPS SMEM layout ----------------
#define OFF_PT     0u          // 3072 float4 = 49152
#define OFF_MIND   49152u      // 3072 float  = 12288
#define OFF_CST    61440u      // 65 int -> 264
#define OFF_UB     61704u      // 64 float
#define OFF_KLO    61960u      // 64 uint
#define OFF_WP     62224u      // 64 float4 (16-aligned)
#define OFF_WC     63248u      // 64 int (per-warp cell lists)
#define OFF_WCNT   63504u      // 8 int
#define OFF_MYSLOT 63536u      // 32 B
#define OFF_SLOTS  63568u      // 2*8*32 = 512
#define OFF_MBAR   64080u      // 2 mbarriers
#define FPS_SMEM   64096u

// ---------------- FPS body: 8-CTA cluster, SMEM-resident, mbarrier comm ----------------
__device__ void fps_cluster(unsigned char* s_raw) {
    float4*   s_pt   = (float4*)(s_raw + OFF_PT);
    float*    s_mind = (float*)(s_raw + OFF_MIND);
    int*      s_cst  = (int*)(s_raw + OFF_CST);
    float*    s_ub   = (float*)(s_raw + OFF_UB);
    unsigned* s_klo  = (unsigned*)(s_raw + OFF_KLO);
    float4*   s_wp   = (float4*)(s_raw + OFF_WP);
    int*      s_wc   = (int*)(s_raw + OFF_WC);
    int*      s_wcnt = (int*)(s_raw + OFF_WCNT);

    const int tid = threadIdx.x, lane = tid & 31, wid = tid >> 5;
    const unsigned FULL = 0xffffffffu;
    const float INF = __int_as_float(0x7f800000);
    const unsigned rank = cl_rank();

    const unsigned mbar_base  = smem_u32(s_raw + OFF_MBAR);
    const unsigned slots_lcl  = smem_u32(s_raw + OFF_SLOTS);

    // ---- init: load slab into SMEM ----
    int base  = g_cellstart[rank * 64];
    int count = min(g_cellstart[rank * 64 + 64] - base, SLAB_MAX);
    for (int i = tid; i <= 64; i += 512)
        s_cst[i] = min(g_cellstart[rank * 64 + i] - base, SLAB_MAX);
    for (int i = tid; i < count; i += 512) {
        s_pt[i] = g_spos[base + i];
        s_mind[i] = INF;
    }
    if (tid < 8) s_wcnt[tid] = 0;
    __syncthreads();
    if (tid < 64) {
        s_ub[tid]  = (s_cst[tid + 1] > s_cst[tid]) ? INF : 0.0f;
        s_klo[tid] = 0u;
        int w = (3 * (tid >> 3) + (tid & 7)) & 7;   // balanced interleave
        int p = atomicAdd(&s_wcnt[w], 1);
        s_wc[w * 8 + p] = tid;
    }
    if (tid == 0) {
        asm volatile("mbarrier.init.shared.b64 [%0], %1;" :: "r"(mbar_base),     "r"(CL) : "memory");
        asm volatile("mbarrier.init.shared.b64 [%0], %1;" :: "r"(mbar_base + 8), "r"(CL) : "memory");
        if (rank == 0) g_idx[0] = 0;
    }
    __syncthreads();
    CL_SYNC();                         // mbarriers visible cluster-wide

    // this warp's static cell list + geometry in registers
    int   jreg[8]; float lyr[8], lzr[8];
    #pragma unroll
    for (int i = 0; i < 8; ++i) {
        int j = s_wc[wid * 8 + i];
        jreg[i] = j;
        lyr[i] = (float)((j >> 3) & 7) * 0.125f;
        lzr[i] = (float)(j & 7) * 0.125f;
    }
    const float lx0 = (float)rank * 0.125f;

    float4 q0 = g_pos4[0];
    float qx = q0.x, qy = q0.y, qz = q0.z;

    for (int t = 0; t < Mm - 1; ++t) {
        const int buf = t & 1;
        const int parity = (t >> 1) & 1;
        // ---- fused activity + update over this warp's 8 cells ----
        float dxs = fmaxf(fmaxf(lx0 - qx, qx - (lx0 + 0.125f)), 0.0f);
        dxs *= dxs;
        unsigned amask = 0;
        #pragma unroll
        for (int i = 0; i < 8; ++i) {
            float dy = fmaxf(fmaxf(lyr[i] - qy, qy - (lyr[i] + 0.125f)), 0.0f);
            float dz = fmaxf(fmaxf(lzr[i] - qz, qz - (lzr[i] + 0.125f)), 0.0f);
            float lb2 = dxs + dy * dy + dz * dz;
            if (lb2 * 0.99999f < s_ub[jreg[i]]) amask |= (1u << i);
        }
        while (amask) {                          // warp-uniform
            int i = __ffs(amask) - 1; amask &= amask - 1;
            int j = jreg[i];
            int st = s_cst[j], en = s_cst[j + 1];
            float bv = -1.0f; int bidx = 0x7FFFFFFF;
            float bx = 0.f, by = 0.f, bz = 0.f;
            for (int k = st + lane; k < en; k += 32) {
                float4 p = s_pt[k];
                float ddx = p.x - qx, ddy = p.y - qy, ddz = p.z - qz;
                float d2 = __fadd_rn(__fadd_rn(__fmul_rn(ddx, ddx),
                                               __fmul_rn(ddy, ddy)),
                                     __fmul_rn(ddz, ddz));
                float nm = fminf(s_mind[k], d2);
                s_mind[k] = nm;
                int oi = __float_as_int(p.w);
                if (nm > bv || (nm == bv && oi < bidx)) {
                    bv = nm; bidx = oi; bx = p.x; by = p.y; bz = p.z;
                }
            }
            unsigned vb = (bv < 0.f) ? 0u : __float_as_uint(bv);
            unsigned mv = __reduce_max_sync(FULL, vb);
            unsigned ci = (vb == mv) ? (unsigned)bidx : 0xFFFFFFFFu;
            unsigned mi = __reduce_min_sync(FULL, ci);
            if (vb == mv && (unsigned)bidx == mi) {   // unique winner lane
                s_ub[j]  = __uint_as_float(mv);
                s_klo[j] = 0xFFFFFFFFu - mi;
                s_wp[j]  = make_float4(bx, by, bz, 0.f);
            }
        }
        __syncthreads();                              // S1
        // ---- warp 0: local argmax over 64 cells, push slot to all CTAs ----
        if (wid == 0) {
            unsigned long long k0 =
                ((unsigned long long)__float_as_uint(s_ub[lane]) << 32) | s_klo[lane];
            unsigned long long k1 =
                ((unsigned long long)__float_as_uint(s_ub[lane + 32]) << 32) | s_klo[lane + 32];
            int bj = lane; unsigned long long bk = k0;
            if (k1 > k0) { bk = k1; bj = lane + 32; }
            unsigned hi = (unsigned)(bk >> 32), lo = (unsigned)bk;
            unsigned mhi = __reduce_max_sync(FULL, hi);
            unsigned lo2 = (hi == mhi) ? lo : 0u;
            unsigned mlo = __reduce_max_sync(FULL, lo2);
            if (hi == mhi && lo == mlo) {             // unique local winner lane
                float4 wp = s_wp[bj];
                unsigned long long* ms = (unsigned long long*)(s_raw + OFF_MYSLOT);
                ms[0] = bk;
                float* msf = (float*)(s_raw + OFF_MYSLOT + 8);
                msf[0] = wp.x; msf[1] = wp.y; msf[2] = wp.z;
            }
            __syncwarp();
            if (lane < CL) {
                unsigned long long key = *(unsigned long long*)(s_raw + OFF_MYSLOT);
                float x = *(float*)(s_raw + OFF_MYSLOT + 8);
                float y = *(float*)(s_raw + OFF_MYSLOT + 12);
                float z = *(float*)(s_raw + OFF_MYSLOT + 16);
                dsmem_push_slot(slots_lcl + buf * 256 + rank * 32,
                                mbar_base + buf * 8, (unsigned)lane, key, x, y, z);
            }
        }
        __syncthreads();                              // S2
        // ---- all warps: wait + combine (safe: peers' iter t+2 slot writes
        //      require our arrive(t+1), which follows all warps' S1(t+1),
        //      which follows these reads and this wait) ----
        MBAR_WAIT_CLUSTER(mbar_base + buf * 8, parity);
        unsigned long long key = 0ull; float sx = 0.f, sy = 0.f, sz = 0.f;
        if (lane < CL) {
            unsigned char* sl = s_raw + OFF_SLOTS + buf * 256 + lane * 32;
            key = *(unsigned long long*)sl;
            sx = *(float*)(sl + 8); sy = *(float*)(sl + 12); sz = *(float*)(sl + 16);
        }
        unsigned hi = (unsigned)(key >> 32), lo = (unsigned)key;
        unsigned mhi = __reduce_max_sync(FULL, hi);
        unsigned lo2 = (hi == mhi) ? lo : 0u;
        unsigned mlo = __reduce_max_sync(FULL, lo2);
        bool win = (hi == mhi) && (lo == mlo) && (lane < CL);
        int wl = __ffs(__ballot_sync(FULL, win)) - 1;
        qx = __shfl_sync(FULL, sx, wl);
        qy = __shfl_sync(FULL, sy, wl);
        qz = __shfl_sync(FULL, sz, wl);
        if (rank == 0 && wid == 0 && win)
            g_idx[t + 1] = (int)(0xFFFFFFFFu - mlo);
    }

    // ---- teardown: invalidate mbarriers so graph replays can re-init.
    //      (mbarrier.init on a still-valid barrier is UB -> the mid-warmup
    //      illegal-instruction trap of round 8.)
    __syncthreads();
    CL_SYNC();      // all remote arrives/reads for the final phase are drained
    if (tid == 0) {
        asm volatile("mbarrier.inval.shared.b64 [%0];" :: "r"(mbar_base)     : "memory");
        asm volatile("mbarrier.inval.shared.b64 [%0];" :: "r"(mbar_base + 8) : "memory");
    }
    __syncthreads();
    CL_SYNC();      // no CTA exits while peers could still address its SMEM
}

// ---------------- scatter body: all edges, all nodes, warp per edge ----------------
__device__ void scatter_all(const float* __restrict__ x,
                            const int*   __restrict__ ei,
                            const float* __restrict__ ea,
                            int cta, int nctas) {
    int lane = threadIdx.x & 31;
    int gw   = cta * 16 + (threadIdx.x >> 5);
    int nw   = nctas * 16;
    for (int e = gw; e < Ee; e += nw) {
        int dst = __ldg(&ei[Ee + e]);
        int src = __ldg(&ei[e]);
        float v0 = __fmul_rn(__ldg(&ea[3 * e + 0]), 2.0f);
        float v1 = __fmul_rn(__ldg(&ea[3 * e + 1]), 2.0f);
        float v2 = __fmul_rn(__ldg(&ea[3 * e + 2]), 2.0f);
        float k0 = fminf(fmaxf(floorf(v0), 0.f), 1.f);
        float k1 = fminf(fmaxf(floorf(v1), 0.f), 1.f);
        float k2 = fminf(fmaxf(floorf(v2), 0.f), 1.f);
        float f0 = v0 - k0, f1 = v1 - k1, f2 = v2 - k2;
        int pb = (int)k0 * 9 + (int)k1 * 3 + (int)k2;
        float xj0 = __ldg(&x[(size_t)src * KIN + lane]);
        float xj1 = __ldg(&x[(size_t)src * KIN + 32 + lane]);
        float* accb = g_accN + (size_t)dst * PIN;
        #pragma unroll
        for (int s = 0; s < 8; ++s) {
            int b0 = s & 1, b1 = (s >> 1) & 1, b2 = (s >> 2) & 1;
            float b = b0 ? f0 : (1.0f - f0);
            b = __fmul_rn(b, b1 ? f1 : (1.0f - f1));
            b = __fmul_rn(b, b2 ? f2 : (1.0f - f2));
            int off = (pb + b0 * 9 + b1 * 3 + b2) * KIN;
            atomicAdd(&accb[off + lane],      __fmul_rn(b, xj0));
            atomicAdd(&accb[off + 32 + lane], __fmul_rn(b, xj1));
        }
        if (lane == 0) atomicAdd(&g_degN[dst], 1.0f);
    }
}

// ---------------- launch 4 (FAT): blocks 0-7 = FPS cluster, 8-143 = scatter ----------------
__global__ void __launch_bounds__(512, 1) __cluster_dims__(CL, 1, 1)
fat_kernel(const float* __restrict__ x,
           const int*   __restrict__ ei,
           const float* __restrict__ ea) {
    extern __shared__ unsigned char s_raw[];
    if (blockIdx.x < CL) fps_cluster(s_raw);
    else scatter_all(x, ei, ea, blockIdx.x - CL, gridDim.x - CL);
}

// ---------------- launch 5: gather-GEMM + root + bias + ELU (20 nodes/block) ----------------
#define NB 20
__global__ void __launch_bounds__(64) node_out_kernel(const float* __restrict__ x,
                                                      const float* __restrict__ W,
                                                      const float* __restrict__ rootw,
                                                      const float* __restrict__ bias,
                                                      float* __restrict__ out) {
    int m0 = blockIdx.x * NB;
    int o  = threadIdx.x;
    int nodes[NB];
    #pragma unroll
    for (int j = 0; j < NB; ++j) nodes[j] = g_idx[m0 + j];
    float s[NB];
    #pragma unroll
    for (int j = 0; j < NB; ++j) s[j] = 0.f;
    #pragma unroll 2
    for (int k = 0; k < PIN; ++k) {
        float w = __ldg(&W[k * KIN + o]);
        #pragma unroll
        for (int j = 0; j < NB; ++j)
            s[j] += __ldg(&g_accN[(size_t)nodes[j] * PIN + k]) * w;
    }
    float b = bias[o];
    for (int j = 0; j < NB; ++j) {
        int m = m0 + j;
        float v = s[j] / fmaxf(g_degN[nodes[j]], 1.0f);
        const float* xr = x + (size_t)nodes[j] * KIN;
        #pragma unroll 8
        for (int i = 0; i < KIN; ++i)
            v += __ldg(&xr[i]) * __ldg(&rootw[i * KIN + o]);
        v += b;
        v = (v > 0.f) ? v : expm1f(v);
        out[SEC_X + m * KIN + o] = v;
    }
}

// ---------------- launch 6: radius via grid + bitmap, ordered emit ----------------
#define RW 625
__global__ void __launch_bounds__(128) radius_kernel(float* __restrict__ out) {
    __shared__ unsigned s_bm[RW];
    __shared__ int s_cells[32];
    __shared__ int s_ncell;
    int m = blockIdx.x, tid = threadIdx.x;
    int node = g_idx[m];
    float4 q = g_pos4[node];
    for (int i = tid; i < RW; i += 128) s_bm[i] = 0u;
    if (tid == 0) {
        int lo[3], hi[3];
        float qc[3] = {q.x, q.y, q.z};
        for (int d = 0; d < 3; ++d) {
            lo[d] = max(0, (int)floorf((qc[d] - 0.1f) * 8.0f - 1e-3f));
            hi[d] = min(7, (int)floorf((qc[d] + 0.1f) * 8.0f + 1e-3f));
        }
        int n = 0;
        for (int cx = lo[0]; cx <= hi[0]; ++cx)
            for (int cy = lo[1]; cy <= hi[1]; ++cy)
                for (int cz = lo[2]; cz <= hi[2]; ++cz)
                    s_cells[n++] = (cx << 6) | (cy << 3) | cz;
        s_ncell = n;
    }
    __syncthreads();
    int nc = s_ncell;
    for (int ci = 0; ci < nc; ++ci) {
        int cid = s_cells[ci];
        int st = g_cellstart[cid], en = g_cellstart[cid + 1];
        for (int i = st + tid; i < en; i += 128) {
            float4 p = __ldg(&g_spos[i]);
            float an = __fadd_rn(__fadd_rn(__fmul_rn(p.x, p.x), __fmul_rn(p.y, p.y)),
                                 __fmul_rn(p.z, p.z));
            float dot = __fadd_rn(__fadd_rn(__fmul_rn(q.x, p.x), __fmul_rn(q.y, p.y)),
                                  __fmul_rn(q.z, p.z));
            float d2 = __fadd_rn(__fadd_rn(q.w, an), -__fmul_rn(2.0f, dot));
            if (d2 < R2c) {
                int oi = __float_as_int(p.w);
                atomicOr(&s_bm[oi >> 5], 1u << (oi & 31));
            }
        }
    }
    __syncthreads();
    if (tid < 32) {
        int lane = tid;
        int base = 0;
        for (int w0 = 0; w0 < RW; w0 += 32) {
            unsigned word = (w0 + lane < RW) ? s_bm[w0 + lane] : 0u;
            int pc = __popc(word);
            int ex = pc;
            #pragma unroll
            for (int o = 1; o < 32; o <<= 1) {
                int v = __shfl_up_sync(0xffffffffu, ex, o);
                if (lane >= o) ex += v;
            }
            int tot = __shfl_sync(0xffffffffu, ex, 31);
            ex -= pc;
            int pos = base + ex;
            while (word && pos < MAXNb) {
                int b = __ffs(word) - 1;
                word &= word - 1;
                int oi = (w0 + lane) * 32 + b;
                out[SEC_COL + m * MAXNb + pos] = (float)oi;
                out[SEC_ROW + m * MAXNb + pos] = (float)m;
                ++pos;
            }
            base += tot;
            if (base >= MAXNb) break;
        }
        for (int j = base + lane; j < MAXNb; j += 32) {
            out[SEC_COL + m * MAXNb + j] = -1.0f;
            out[SEC_ROW + m * MAXNb + j] = -1.0f;
        }
    }
}

// ---------------- launch 7: tail gathers ----------------
__global__ void tail_kernel(const float* __restrict__ pos,
                            const float* __restrict__ ea,
                            float* __restrict__ out) {
    int m = blockIdx.x * blockDim.x + threadIdx.x;
    if (m >= Mm) return;
    int node = g_idx[m];
    out[SEC_POS + 3 * m + 0] = pos[3 * node + 0];
    out[SEC_POS + 3 * m + 1] = pos[3 * node + 1];
    out[SEC_POS + 3 * m + 2] = pos[3 * node + 2];
    out[SEC_BATCH + m]       = 0.0f;
    out[SEC_EA + 3 * m + 0]  = ea[3 * node + 0];
    out[SEC_EA + 3 * m + 1]  = ea[3 * node + 1];
    out[SEC_EA + 3 * m + 2]  = ea[3 * node + 2];
}

// ---------------- launch ----------------
extern "C" void kernel_launch(void* const* d_in, const int* in_sizes, int n_in,
                              void* d_out, int out_size) {
    const float* x     = (const float*)d_in[0];
    const int*   ei    = (const int*)d_in[1];
    const float* ea    = (const float*)d_in[2];
    const float* pos   = (const float*)d_in[3];
    const float* W     = (const float*)d_in[5];
    const float* rootw = (const float*)d_in[6];
    const float* bias  = (const float*)d_in[7];
    float* out = (float*)d_out;

    cudaFuncSetAttribute(fat_kernel, cudaFuncAttributeMaxDynamicSharedMemorySize,
                         FPS_SMEM);

    prep1b_kernel<<<1, 1024>>>(pos);                 // 1
    cell_scan_kernel<<<1, NC>>>();                   // 2
    scatter_zero_kernel<<<ZB, 256>>>(pos);           // 3
    fat_kernel<<<144, 512, FPS_SMEM>>>(x, ei, ea);   // 4 (grid % 8 == 0; ncu target)
    node_out_kernel<<<Mm / NB, KIN>>>(x, W, rootw, bias, out); // 5
    radius_kernel<<<Mm, 128>>>(out);                 // 6
    tail_kernel<<<(Mm + 127) / 128, 128>>>(pos, ea, out);      // 7
}

// round 10
// speedup vs baseline: 1.3803x; 1.3803x over previous
#include <cuda_runtime.h>
#include <math.h>

// ---------------- problem constants ----------------
#define Nn    20000
#define Ee    640000
#define Pp    27
#define Mm    5000
#define MAXNb 64
#define KIN   64
#define PIN   (Pp * KIN)      // 1728
#define R2c   0.01f
#define NC    512             // 8x8x8 spatial cells
#define CL    2               // FPS cluster size (half the cloud per CTA)
#define SLAB_MAX 10560        // max points per half (mean 10000, +8 sigma)

// output section offsets (flattened float32 tuple concat)
#define SEC_X     0
#define SEC_COL   320000
#define SEC_ROW   640000
#define SEC_POS   960000
#define SEC_BATCH 975000
#define SEC_EA    980000

// ---------------- persistent device scratch ----------------
__device__ __align__(16) float4 g_pos4[Nn];   // x,y,z, |p|^2
__device__ int    g_idx[Mm];
__device__ int    g_pcell[Nn];
__device__ int    g_cellcnt[NC];
__device__ int    g_cellstart[NC + 1];
__device__ int    g_cellfill[NC];
__device__ __align__(16) float4 g_spos[Nn];   // cell-sorted: x,y,z, orig idx bits
__device__ __align__(16) float g_accN[(size_t)Nn * PIN];  // 138 MB, all nodes
__device__ float  g_degN[Nn];

// ---------------- launch 1: pos4 + cell id + histogram (single block) ----------------
__global__ void __launch_bounds__(1024) prep1b_kernel(const float* __restrict__ pos) {
    int tid = threadIdx.x;
    if (tid < NC) g_cellcnt[tid] = 0;
    __syncthreads();
    for (int i = tid; i < Nn; i += 1024) {
        float x = pos[3 * i], y = pos[3 * i + 1], z = pos[3 * i + 2];
        float an = __fadd_rn(__fadd_rn(__fmul_rn(x, x), __fmul_rn(y, y)),
                             __fmul_rn(z, z));
        g_pos4[i] = make_float4(x, y, z, an);
        int cx = min((int)(x * 8.0f), 7);
        int cy = min((int)(y * 8.0f), 7);
        int cz = min((int)(z * 8.0f), 7);
        int cid = (cx << 6) | (cy << 3) | cz;
        g_pcell[i] = cid;
        atomicAdd(&g_cellcnt[cid], 1);
    }
}

// ---------------- launch 2: exclusive scan of cell counts ----------------
__global__ void cell_scan_kernel() {
    __shared__ int sh[NC];
    int tid = threadIdx.x;
    int v = g_cellcnt[tid];
    sh[tid] = v;
    __syncthreads();
    for (int o = 1; o < NC; o <<= 1) {
        int t = (tid >= o) ? sh[tid - o] : 0;
        __syncthreads();
        sh[tid] += t;
        __syncthreads();
    }
    g_cellstart[tid + 1] = sh[tid];
    g_cellfill[tid] = sh[tid] - v;
    if (tid == 0) g_cellstart[0] = 0;
}

// ---------------- launch 3: cell scatter + zero acc/deg (fused) ----------------
#define ZB 33750   // 33750*256 float4 = Nn*PIN floats
__global__ void scatter_zero_kernel(const float* __restrict__ pos) {
    int i = blockIdx.x * blockDim.x + threadIdx.x;
    if (i < Nn) {
        int cid = g_pcell[i];
        int off = atomicAdd(&g_cellfill[cid], 1);
        g_spos[off] = make_float4(pos[3 * i], pos[3 * i + 1], pos[3 * i + 2],
                                  __int_as_float(i));
        g_degN[i] = 0.0f;
    }
    reinterpret_cast<float4*>(g_accN)[i] = make_float4(0.f, 0.f, 0.f, 0.f);
}

// ---------------- FPS cluster helpers ----------------
__device__ __forceinline__ unsigned smem_u32(const void* p) {
    unsigned a;
    asm("{ .reg .u64 t; cvta.to.shared.u64 t, %1; cvt.u32.u64 %0, t; }"
        : "=r"(a) : "l"(p));
    return a;
}
__device__ __forceinline__ unsigned cl_rank() {
    unsigned r;
    asm("mov.u32 %0, %%cluster_ctarank;" : "=r"(r));
    return r;
}
#define CL_SYNC() do { \
    asm volatile("barrier.cluster.arrive.aligned;" ::: "memory"); \
    asm volatile("barrier.cluster.wait.aligned;" ::: "memory"); } while (0)

#define MBAR_WAIT_CLUSTER(mbar, par) do { \
    asm volatile("{\n\t.reg .pred p;\n\t" \
        "WAITC_%=:\n\t" \
        "mbarrier.try_wait.parity.acquire.cluster.shared::cta.b64 p, [%0], %1;\n\t" \
        "@p bra.uni DONEC_%=;\n\t" \
        "bra.uni WAITC_%=;\n\t" \
        "DONEC_%=:\n\t}" :: "r"(mbar), "r"(par) : "memory"); } while (0)

// store 32B slot {key, x, y, z} into PEER's smem + arrive on PEER's mbarrier
__device__ __forceinline__ void dsmem_push_slot(unsigned slot_addr, unsigned mbar_addr,
                                                unsigned target,
                                                unsigned long long key,
                                                float x, float y, float z) {
    unsigned rs, rb;
    asm volatile("mapa.shared::cluster.u32 %0, %1, %2;"
                 : "=r"(rs) : "r"(slot_addr), "r"(target));
    asm volatile("mapa.shared::cluster.u32 %0, %1, %2;"
                 : "=r"(rb) : "r"(mbar_addr), "r"(target));
    asm volatile("st.shared::cluster.u64 [%0], %1;" :: "r"(rs), "l"(key) : "memory");
    asm volatile("st.shared::cluster.b32 [%0], %1;" :: "r"(rs + 8),  "r"(__float_as_uint(x)) : "memory");
    asm volatile("st.shared::cluster.b32 [%0], %1;" :: "r"(rs + 12), "r"(__float_as_uint(y)) : "memory");
    asm volatile("st.shared::cluster.b32 [%0], %1;" :: "r"(rs + 16), "r"(__float_as_uint(z)) : "memory");
    asm volatile("mbarrier.arrive.release.cluster.shared::cluster.b64 _, [%0];"
                 :: "r"(rb) : "memory");
}

// ---------------- FPS SMEM layout (2-CTA version, half cloud resident) ----------------
#define OFF_PT     0u                         // SLAB_MAX*16 = 168960
#define OFF_MIND   168960u                    // SLAB_MAX*4  = 42240
#define OFF_CST    211200u                    // 257*4 -> pad 1040
#define OFF_KEY    212240u                    // 256 u64 = 2048
#define OFF_CWP    214288u                    // 256 float4 = 4096
#define OFF_SLOTS  218384u                    // 2 bufs * 2 ctas * 32B = 128
#define OFF_MBAR   218512u                    // 2 mbarriers
#define FPS_SMEM   218528u

// ---------------- FPS body: 2-CTA cluster, 1 barrier/iter, trivial combine ----------------
__device__ void fps_cluster(unsigned char* s_raw) {
    float4*             s_pt   = (float4*)(s_raw + OFF_PT);
    float*              s_mind = (float*)(s_raw + OFF_MIND);
    int*                s_cst  = (int*)(s_raw + OFF_CST);
    unsigned long long* s_key  = (unsigned long long*)(s_raw + OFF_KEY);
    float4*             s_cwp  = (float4*)(s_raw + OFF_CWP);

    const int tid = threadIdx.x, lane = tid & 31, wid = tid >> 5;
    const unsigned FULL = 0xffffffffu;
    const float INF = __int_as_float(0x7f800000);
    const unsigned rank = cl_rank();

    const unsigned mbar_base = smem_u32(s_raw + OFF_MBAR);

    // ---- per-lane owned cell (bijective balanced map: 16 cells/warp) ----
    // cell c (local 0..255): cx4=(c>>6)&3, cy=(c>>3)&7, cz=c&7
    // warp(c) = ((cz + 2*cx4)&7) | (((cy^cx4)&1)<<3); lane-slot = cx4*4 + cy/2
    int l   = lane & 15;
    int cx4 = l >> 2, cyi = l & 3;
    int cz  = ((wid & 7) - 2 * cx4) & 7;
    int par0 = ((wid >> 3) ^ cx4) & 1;
    int cy  = 2 * cyi + par0;
    int cid = (cx4 << 6) | (cy << 3) | cz;
    const float lx = (float)((int)rank * 4 + cx4) * 0.125f;
    const float ly = (float)cy * 0.125f;
    const float lz = (float)cz * 0.125f;

    // ---- init: load half-cloud into SMEM ----
    int base  = g_cellstart[rank * 256];
    int count = min(g_cellstart[rank * 256 + 256] - base, SLAB_MAX);
    if (tid <= 256)
        s_cst[tid] = min(g_cellstart[rank * 256 + tid] - base, SLAB_MAX);
    for (int i = tid; i < count; i += 512) {
        s_pt[i] = g_spos[base + i];
        s_mind[i] = INF;
    }
    __syncthreads();
    if (tid < 256)
        s_key[tid] = (s_cst[tid + 1] > s_cst[tid]) ? (0x7f800000ULL << 32) : 0ULL;
    int st_l = s_cst[cid], en_l = s_cst[cid + 1];
    if (tid == 0) {
        asm volatile("mbarrier.init.shared.b64 [%0], %1;" :: "r"(mbar_base),     "r"(2) : "memory");
        asm volatile("mbarrier.init.shared.b64 [%0], %1;" :: "r"(mbar_base + 8), "r"(2) : "memory");
        if (rank == 0) g_idx[0] = 0;
    }
    __syncthreads();
    CL_SYNC();                         // mbarriers + tiles visible cluster-wide

    float4 q0 = g_pos4[0];
    float qx = q0.x, qy = q0.y, qz = q0.z;

    for (int t = 0; t < Mm - 1; ++t) {
        const int buf = t & 1;
        const int parity = (t >> 1) & 1;
        // ---- activity (lane-parallel, no barrier) ----
        float dx = fmaxf(fmaxf(lx - qx, qx - (lx + 0.125f)), 0.0f);
        float dy = fmaxf(fmaxf(ly - qy, qy - (ly + 0.125f)), 0.0f);
        float dz = fmaxf(fmaxf(lz - qz, qz - (lz + 0.125f)), 0.0f);
        float lb2 = dx * dx + dy * dy + dz * dz;
        float ub = ((float*)s_key)[2 * cid + 1];     // hi word (ub >= 0)
        bool act = (lane < 16) && (lb2 * 0.99999f < ub);
        unsigned bal = __ballot_sync(FULL, act);
        // ---- update active cells (warp-serial, typically 0-2) ----
        while (bal) {
            int i = __ffs(bal) - 1; bal &= bal - 1;
            int ci = __shfl_sync(FULL, cid, i);
            int st = __shfl_sync(FULL, st_l, i);
            int en = __shfl_sync(FULL, en_l, i);
            float bv = -1.0f; int bidx = 0x7FFFFFFF;
            float bx = 0.f, by = 0.f, bz = 0.f;
            for (int k = st + lane; k < en; k += 32) {
                float4 p = s_pt[k];
                float ddx = p.x - qx, ddy = p.y - qy, ddz = p.z - qz;
                float d2 = __fadd_rn(__fadd_rn(__fmul_rn(ddx, ddx),
                                               __fmul_rn(ddy, ddy)),
                                     __fmul_rn(ddz, ddz));
                float nm = fminf(s_mind[k], d2);
                s_mind[k] = nm;
                int oi = __float_as_int(p.w);
                if (nm > bv || (nm == bv && oi < bidx)) {
                    bv = nm; bidx = oi; bx = p.x; by = p.y; bz = p.z;
                }
            }
            unsigned vb = (bv < 0.f) ? 0u : __float_as_uint(bv);
            unsigned mv = __reduce_max_sync(FULL, vb);
            unsigned ciw = (vb == mv) ? (unsigned)bidx : 0xFFFFFFFFu;
            unsigned mi = __reduce_min_sync(FULL, ciw);
            if (vb == mv && (unsigned)bidx == mi) {   // unique winner lane
                s_key[ci] = ((unsigned long long)mv << 32) |
                            (unsigned long long)(0xFFFFFFFFu - mi);
                s_cwp[ci] = make_float4(bx, by, bz, 0.f);
            }
        }
        __syncthreads();                              // S1 (the only block barrier)
        // ---- warp 0: scan 256 keys, push slot to peer, arrive both ----
        if (wid == 0) {
            unsigned long long best = 0ull; int bc = lane;
            #pragma unroll
            for (int j = 0; j < 8; ++j) {
                unsigned long long k = s_key[lane + (j << 5)];
                if (k > best) { best = k; bc = lane + (j << 5); }
            }
            unsigned hi = (unsigned)(best >> 32), lo = (unsigned)best;
            unsigned mhi = __reduce_max_sync(FULL, hi);
            unsigned lo2 = (hi == mhi) ? lo : 0u;
            unsigned mlo = __reduce_max_sync(FULL, lo2);
            if (hi == mhi && lo == mlo) {             // unique (lo embeds idx)
                float4 wp = s_cwp[bc];
                unsigned char* sl = s_raw + OFF_SLOTS + buf * 64 + rank * 32;
                *(unsigned long long*)sl = best;
                ((float*)sl)[2] = wp.x;
                ((float*)sl)[3] = wp.y;
                ((float*)sl)[4] = wp.z;
                dsmem_push_slot(smem_u32(sl), mbar_base + buf * 8,
                                rank ^ 1u, best, wp.x, wp.y, wp.z);
                asm volatile("mbarrier.arrive.shared.b64 _, [%0];"
                             :: "r"(mbar_base + buf * 8) : "memory");  // local arrive
            }
        }
        // ---- everyone: wait (count=2), combine the two slots directly ----
        MBAR_WAIT_CLUSTER(mbar_base + buf * 8, parity);
        unsigned char* s0 = s_raw + OFF_SLOTS + buf * 64;
        unsigned long long k0 = *(unsigned long long*)s0;
        unsigned long long k1 = *(unsigned long long*)(s0 + 32);
        unsigned char* sw = (k1 > k0) ? (s0 + 32) : s0;
        qx = ((float*)sw)[2]; qy = ((float*)sw)[3]; qz = ((float*)sw)[4];
        if (rank == 0 && tid == 0) {
            unsigned long long kw = (k1 > k0) ? k1 : k0;
            g_idx[t + 1] = (int)(0xFFFFFFFFu - (unsigned)(kw & 0xFFFFFFFFull));
        }
    }

    // ---- teardown: inval mbarriers for graph-replay safety (R8 trap fix) ----
    __syncthreads();
    CL_SYNC();
    if (tid == 0) {
        asm volatile("mbarrier.inval.shared.b64 [%0];" :: "r"(mbar_base)     : "memory");
        asm volatile("mbarrier.inval.shared.b64 [%0];" :: "r"(mbar_base + 8) : "memory");
    }
    __syncthreads();
    CL_SYNC();
}

// ---------------- scatter body: all edges, all nodes, warp per edge ----------------
__device__ void scatter_all(const float* __restrict__ x,
                            const int*   __restrict__ ei,
                            const float* __restrict__ ea,
                            int cta, int nctas) {
    int lane = threadIdx.x & 31;
    int gw   = cta * 16 + (threadIdx.x >> 5);
    int nw   = nctas * 16;
    for (int e = gw; e < Ee; e += nw) {
        int dst = __ldg(&ei[Ee + e]);
        int src = __ldg(&ei[e]);
        float v0 = __fmul_rn(__ldg(&ea[3 * e + 0]), 2.0f);
        float v1 = __fmul_rn(__ldg(&ea[3 * e + 1]), 2.0f);
        float v2 = __fmul_rn(__ldg(&ea[3 * e + 2]), 2.0f);
        float k0 = fminf(fmaxf(floorf(v0), 0.f), 1.f);
        float k1 = fminf(fmaxf(floorf(v1), 0.f), 1.f);
        float k2 = fminf(fmaxf(floorf(v2), 0.f), 1.f);
        float f0 = v0 - k0, f1 = v1 - k1, f2 = v2 - k2;
        int pb = (int)k0 * 9 + (int)k1 * 3 + (int)k2;
        float xj0 = __ldg(&x[(size_t)src * KIN + lane]);
        float xj1 = __ldg(&x[(size_t)src * KIN + 32 + lane]);
        float* accb = g_accN + (size_t)dst * PIN;
        #pragma unroll
        for (int s = 0; s < 8; ++s) {
            int b0 = s & 1, b1 = (s >> 1) & 1, b2 = (s >> 2) & 1;
            float b = b0 ? f0 : (1.0f - f0);
            b = __fmul_rn(b, b1 ? f1 : (1.0f - f1));
            b = __fmul_rn(b, b2 ? f2 : (1.0f - f2));
            int off = (pb + b0 * 9 + b1 * 3 + b2) * KIN;
            atomicAdd(&accb[off + lane],      __fmul_rn(b, xj0));
            atomicAdd(&accb[off + 32 + lane], __fmul_rn(b, xj1));
        }
        if (lane == 0) atomicAdd(&g_degN[dst], 1.0f);
    }
}

// ---------------- launch 4 (FAT): blocks 0-1 = FPS cluster, 2-143 = scatter ----------------
__global__ void __launch_bounds__(512, 1) __cluster_dims__(CL, 1, 1)
fat_kernel(const float* __restrict__ x,
           const int*   __restrict__ ei,
           const float* __restrict__ ea) {
    extern __shared__ unsigned char s_raw[];
    if (blockIdx.x < CL) fps_cluster(s_raw);
    else scatter_all(x, ei, ea, blockIdx.x - CL, gridDim.x - CL);
}

// ---------------- launch 5: gather-GEMM + root + bias + ELU (20 nodes/block) ----------------
#define NB 20
__global__ void __launch_bounds__(64) node_out_kernel(const float* __restrict__ x,
                                                      const float* __restrict__ W,
                                                      const float* __restrict__ rootw,
                                                      const float* __restrict__ bias,
                                                      float* __restrict__ out) {
    int m0 = blockIdx.x * NB;
    int o  = threadIdx.x;
    int nodes[NB];
    #pragma unroll
    for (int j = 0; j < NB; ++j) nodes[j] = g_idx[m0 + j];
    float s[NB];
    #pragma unroll
    for (int j = 0; j < NB; ++j) s[j] = 0.f;
    #pragma unroll 2
    for (int k = 0; k < PIN; ++k) {
        float w = __ldg(&W[k * KIN + o]);
        #pragma unroll
        for (int j = 0; j < NB; ++j)
            s[j] += __ldg(&g_accN[(size_t)nodes[j] * PIN + k]) * w;
    }
    float b = bias[o];
    for (int j = 0; j < NB; ++j) {
        int m = m0 + j;
        float v = s[j] / fmaxf(g_degN[nodes[j]], 1.0f);
        const float* xr = x + (size_t)nodes[j] * KIN;
        #pragma unroll 8
        for (int i = 0; i < KIN; ++i)
            v += __ldg(&xr[i]) * __ldg(&rootw[i * KIN + o]);
        v += b;
        v = (v > 0.f) ? v : expm1f(v);
        out[SEC_X + m * KIN + o] = v;
    }
}

// ---------------- launch 6: radius via grid + bitmap, ordered emit ----------------
#define RW 625
__global__ void __launch_bounds__(128) radius_kernel(float* __restrict__ out) {
    __shared__ unsigned s_bm[RW];
    __shared__ int s_cells[32];
    __shared__ int s_ncell;
    int m = blockIdx.x, tid = threadIdx.x;
    int node = g_idx[m];
    float4 q = g_pos4[node];
    for (int i = tid; i < RW; i += 128) s_bm[i] = 0u;
    if (tid == 0) {
        int lo[3], hi[3];
        float qc[3] = {q.x, q.y, q.z};
        for (int d = 0; d < 3; ++d) {
            lo[d] = max(0, (int)floorf((qc[d] - 0.1f) * 8.0f - 1e-3f));
            hi[d] = min(7, (int)floorf((qc[d] + 0.1f) * 8.0f + 1e-3f));
        }
        int n = 0;
        for (int cx = lo[0]; cx <= hi[0]; ++cx)
            for (int cy = lo[1]; cy <= hi[1]; ++cy)
                for (int cz = lo[2]; cz <= hi[2]; ++cz)
                    s_cells[n++] = (cx << 6) | (cy << 3) | cz;
        s_ncell = n;
    }
    __syncthreads();
    int nc = s_ncell;
    for (int ci = 0; ci < nc; ++ci) {
        int cid = s_cells[ci];
        int st = g_cellstart[cid], en = g_cellstart[cid + 1];
        for (int i = st + tid; i < en; i += 128) {
            float4 p = __ldg(&g_spos[i]);
            float an = __fadd_rn(__fadd_rn(__fmul_rn(p.x, p.x), __fmul_rn(p.y, p.y)),
                                 __fmul_rn(p.z, p.z));
            float dot = __fadd_rn(__fadd_rn(__fmul_rn(q.x, p.x), __fmul_rn(q.y, p.y)),
                                  __fmul_rn(q.z, p.z));
            float d2 = __fadd_rn(__fadd_rn(q.w, an), -__fmul_rn(2.0f, dot));
            if (d2 < R2c) {
                int oi = __float_as_int(p.w);
                atomicOr(&s_bm[oi >> 5], 1u << (oi & 31));
            }
        }
    }
    __syncthreads();
    if (tid < 32) {
        int lane = tid;
        int base = 0;
        for (int w0 = 0; w0 < RW; w0 += 32) {
            unsigned word = (w0 + lane < RW) ? s_bm[w0 + lane] : 0u;
            int pc = __popc(word);
            int ex = pc;
            #pragma unroll
            for (int o = 1; o < 32; o <<= 1) {
                int v = __shfl_up_sync(0xffffffffu, ex, o);
                if (lane >= o) ex += v;
            }
            int tot = __shfl_sync(0xffffffffu, ex, 31);
            ex -= pc;
            int pos = base + ex;
            while (word && pos < MAXNb) {
                int b = __ffs(word) - 1;
                word &= word - 1;
                int oi = (w0 + lane) * 32 + b;
                out[SEC_COL + m * MAXNb + pos] = (float)oi;
                out[SEC_ROW + m * MAXNb + pos] = (float)m;
                ++pos;
            }
            base += tot;
            if (base >= MAXNb) break;
        }
        for (int j = base + lane; j < MAXNb; j += 32) {
            out[SEC_COL + m * MAXNb + j] = -1.0f;
            out[SEC_ROW + m * MAXNb + j] = -1.0f;
        }
    }
}

// ---------------- launch 7: tail gathers ----------------
__global__ void tail_kernel(const float* __restrict__ pos,
                            const float* __restrict__ ea,
                            float* __restrict__ out) {
    int m = blockIdx.x * blockDim.x + threadIdx.x;
    if (m >= Mm) return;
    int node = g_idx[m];
    out[SEC_POS + 3 * m + 0] = pos[3 * node + 0];
    out[SEC_POS + 3 * m + 1] = pos[3 * node + 1];
    out[SEC_POS + 3 * m + 2] = pos[3 * node + 2];
    out[SEC_BATCH + m]       = 0.0f;
    out[SEC_EA + 3 * m + 0]  = ea[3 * node + 0];
    out[SEC_EA + 3 * m + 1]  = ea[3 * node + 1];
    out[SEC_EA + 3 * m + 2]  = ea[3 * node + 2];
}

// ---------------- launch ----------------
extern "C" void kernel_launch(void* const* d_in, const int* in_sizes, int n_in,
                              void* d_out, int out_size) {
    const float* x     = (const float*)d_in[0];
    const int*   ei    = (const int*)d_in[1];
    const float* ea    = (const float*)d_in[2];
    const float* pos   = (const float*)d_in[3];
    const float* W     = (const float*)d_in[5];
    const float* rootw = (const float*)d_in[6];
    const float* bias  = (const float*)d_in[7];
    float* out = (float*)d_out;

    cudaFuncSetAttribute(fat_kernel, cudaFuncAttributeMaxDynamicSharedMemorySize,
                         FPS_SMEM);

    prep1b_kernel<<<1, 1024>>>(pos);                 // 1
    cell_scan_kernel<<<1, NC>>>();                   // 2
    scatter_zero_kernel<<<ZB, 256>>>(pos);           // 3
    fat_kernel<<<144, 512, FPS_SMEM>>>(x, ei, ea);   // 4 (grid % 2 == 0; ncu target)
    node_out_kernel<<<Mm / NB, KIN>>>(x, W, rootw, bias, out); // 5
    radius_kernel<<<Mm, 128>>>(out);                 // 6
    tail_kernel<<<(Mm + 127) / 128, 128>>>(pos, ea, out);      // 7
}